// round 1
// baseline (speedup 1.0000x reference)
#include <cuda_runtime.h>
#include <math.h>

#define D   512
#define MT  64     // rows per block
#define KT  128    // codes per K-tile
#define DT  64     // depth per smem stage
#define TR  16     // thread rows
#define TC  16     // thread cols
#define R   4      // rows per thread
#define C   8      // codes per thread
#define PITCH 68   // DT + 4 pad (conflict-free float4 LDS)

#define MAXN 32768
#define MAXK 8192

__device__ float g_csq[MAXK];
__device__ float g_zsq[MAXN];
__device__ float g_dmin[MAXN];
__device__ float g_H[MAXN];
__device__ int   g_idx[MAXN];
__device__ float g_loss;

// -------- per-row sum of squares (one warp per row) --------
__global__ void sumsq_kernel(const float* __restrict__ src, int rows, int which) {
    int warp = (blockIdx.x * blockDim.x + threadIdx.x) >> 5;
    int lane = threadIdx.x & 31;
    if (warp >= rows) return;
    const float4* p = (const float4*)(src + (size_t)warp * D);
    float acc = 0.f;
#pragma unroll
    for (int i = 0; i < 4; ++i) {
        float4 v = p[lane + i * 32];
        acc += v.x * v.x + v.y * v.y + v.z * v.z + v.w * v.w;
    }
#pragma unroll
    for (int off = 16; off; off >>= 1) acc += __shfl_down_sync(0xffffffffu, acc, off);
    if (lane == 0) {
        if (which) g_csq[warp] = acc; else g_zsq[warp] = acc;
    }
}

// -------- fused cdist + argmin + online softmax entropy --------
__global__ void __launch_bounds__(256, 2)
dist_kernel(const float* __restrict__ z, const float* __restrict__ cb, int N, int K) {
    extern __shared__ float sm[];
    float* zt = sm;                 // [MT][PITCH]
    float* ct = sm + MT * PITCH;    // [KT][PITCH]

    int t  = threadIdx.x;
    int tr = t / TC;
    int tc = t % TC;
    int n0 = blockIdx.x * MT;

    int ldrow = t >> 4;             // tile-load row
    int ldcol = (t & 15) * 4;       // tile-load col (floats)

    float dmin[R], s[R], tt[R];
    int   arg[R];
    float zsq_r[R];
#pragma unroll
    for (int r = 0; r < R; ++r) {
        dmin[r] = 1e30f; s[r] = 0.f; tt[r] = 0.f; arg[r] = 0;
        zsq_r[r] = __ldg(&g_zsq[n0 + tr * R + r]);
    }

    for (int k0 = 0; k0 < K; k0 += KT) {
        float acc[R][C];
#pragma unroll
        for (int r = 0; r < R; ++r)
#pragma unroll
            for (int c = 0; c < C; ++c) acc[r][c] = 0.f;

        for (int d0 = 0; d0 < D; d0 += DT) {
            __syncthreads();
            // stage z tile [MT][DT]
#pragma unroll
            for (int i = 0; i < MT / 16; ++i) {
                float4 v = *(const float4*)(z + (size_t)(n0 + ldrow + i * 16) * D + d0 + ldcol);
                *(float4*)(zt + (ldrow + i * 16) * PITCH + ldcol) = v;
            }
            // stage codebook tile [KT][DT]
#pragma unroll
            for (int i = 0; i < KT / 16; ++i) {
                float4 v = *(const float4*)(cb + (size_t)(k0 + ldrow + i * 16) * D + d0 + ldcol);
                *(float4*)(ct + (ldrow + i * 16) * PITCH + ldcol) = v;
            }
            __syncthreads();

#pragma unroll
            for (int dq = 0; dq < DT / 4; ++dq) {
                float4 zf[R], cf[C];
#pragma unroll
                for (int r = 0; r < R; ++r)
                    zf[r] = *(const float4*)(zt + (tr * R + r) * PITCH + dq * 4);
#pragma unroll
                for (int c = 0; c < C; ++c)
                    cf[c] = *(const float4*)(ct + (tc + c * TC) * PITCH + dq * 4);
#pragma unroll
                for (int r = 0; r < R; ++r)
#pragma unroll
                    for (int c = 0; c < C; ++c) {
                        acc[r][c] += zf[r].x * cf[c].x;
                        acc[r][c] += zf[r].y * cf[c].y;
                        acc[r][c] += zf[r].z * cf[c].z;
                        acc[r][c] += zf[r].w * cf[c].w;
                    }
            }
        }

        // epilogue: d = sqrt(max(zsq + csq - 2*dot, 0)); online min/softmax
#pragma unroll
        for (int c = 0; c < C; ++c) {
            int code = k0 + tc + c * TC;
            float csq = __ldg(&g_csq[code]);
#pragma unroll
            for (int r = 0; r < R; ++r) {
                float d2 = zsq_r[r] + csq - 2.f * acc[r][c];
                float dd = sqrtf(fmaxf(d2, 0.f));
                float nm = fminf(dmin[r], dd);
                float sc = __expf(nm - dmin[r]);   // 1 if no new min
                float e  = __expf(nm - dd);        // term weight
                s[r]  = s[r]  * sc + e;
                tt[r] = tt[r] * sc + e * dd;
                if (dd < dmin[r]) arg[r] = code;
                dmin[r] = nm;
            }
        }
    }

    // reduce across the 16 lanes (tc) sharing each row; lane tc==0 writes
#pragma unroll
    for (int r = 0; r < R; ++r) {
#pragma unroll
        for (int off = 8; off; off >>= 1) {
            float dm2 = __shfl_down_sync(0xffffffffu, dmin[r], off, 16);
            float s2  = __shfl_down_sync(0xffffffffu, s[r],    off, 16);
            float t2  = __shfl_down_sync(0xffffffffu, tt[r],   off, 16);
            int   a2  = __shfl_down_sync(0xffffffffu, arg[r],  off, 16);
            float nm  = fminf(dmin[r], dm2);
            float sc1 = __expf(nm - dmin[r]);
            float sc2 = __expf(nm - dm2);
            s[r]  = s[r]  * sc1 + s2 * sc2;
            tt[r] = tt[r] * sc1 + t2 * sc2;
            arg[r] = (dm2 < dmin[r]) ? a2 : arg[r];
            dmin[r] = nm;
        }
        if (tc == 0) {
            int row = n0 + tr * R + r;
            g_dmin[row] = dmin[r];
            g_idx[row]  = arg[r];
            // H = lse + sum p*d ; lse = log(s) - dmin
            g_H[row] = __logf(s[r]) - dmin[r] + tt[r] / s[r];
        }
    }
}

// -------- scalar loss reduction --------
__global__ void loss_kernel(int N) {
    __shared__ float sd[1024], sh[1024];
    int t = threadIdx.x;
    float a = 0.f, b = 0.f;
    for (int i = t; i < N; i += 1024) { a += g_dmin[i]; b += g_H[i]; }
    sd[t] = a; sh[t] = b;
    __syncthreads();
    for (int off = 512; off; off >>= 1) {
        if (t < off) { sd[t] += sd[t + off]; sh[t] += sh[t + off]; }
        __syncthreads();
    }
    if (t == 0) g_loss = sd[0] / (float)N + 0.1f * sh[0] / (float)N;
}

// -------- outputs: gather quantized, deviation>eps, broadcast loss --------
__global__ void out_kernel(const float* __restrict__ cb, const float* __restrict__ yb,
                           const float* __restrict__ et, float* __restrict__ out, int N) {
    int warp = (blockIdx.x * blockDim.x + threadIdx.x) >> 5;
    int lane = threadIdx.x & 31;
    if (warp >= N) return;
    int idx = g_idx[warp];
    const float4* crow = (const float4*)(cb + (size_t)idx * D);
    const float4* yrow = (const float4*)(yb + (size_t)warp * D);
    float4*       qrow = (float4*)(out + (size_t)warp * D);
    float acc = 0.f;
#pragma unroll
    for (int i = 0; i < 4; ++i) {
        float4 cv = crow[lane + i * 32];
        float4 yv = yrow[lane + i * 32];
        qrow[lane + i * 32] = cv;
        float dx = cv.x - yv.x, dy = cv.y - yv.y, dz = cv.z - yv.z, dw = cv.w - yv.w;
        acc += dx * dx + dy * dy + dz * dz + dw * dw;
    }
#pragma unroll
    for (int off = 16; off; off >>= 1) acc += __shfl_down_sync(0xffffffffu, acc, off);
    if (lane == 0) {
        float dev = sqrtf(acc);
        out[(size_t)N * D + warp]     = g_loss;                                  // quant_loss (w=1)
        out[(size_t)N * D + N + warp] = et[warp] + (dev > 0.01f ? 1.0f : 0.0f);  // error_times
    }
}

extern "C" void kernel_launch(void* const* d_in, const int* in_sizes, int n_in,
                              void* d_out, int out_size) {
    const float* z  = (const float*)d_in[0];
    const float* yb = (const float*)d_in[1];
    const float* et = (const float*)d_in[2];
    const float* cb = (const float*)d_in[3];
    int N = in_sizes[0] / D;
    int K = in_sizes[3] / D;
    float* out = (float*)d_out;

    const int smem = (MT + KT) * PITCH * (int)sizeof(float);   // 52224 B
    cudaFuncSetAttribute(dist_kernel, cudaFuncAttributeMaxDynamicSharedMemorySize, smem);

    sumsq_kernel<<<(N + 7) / 8, 256>>>(z, N, 0);
    sumsq_kernel<<<(K + 7) / 8, 256>>>(cb, K, 1);
    dist_kernel<<<N / MT, 256, smem>>>(z, cb, N, K);
    loss_kernel<<<1, 1024>>>(N);
    out_kernel<<<(N + 7) / 8, 256>>>(cb, yb, et, out, N);
}